// round 2
// baseline (speedup 1.0000x reference)
#include <cuda_runtime.h>
#include <math.h>

#define Nn 128
#define Cc 256
#define Aa 512

// Scratch (device globals — no allocations allowed)
__device__ float g_U[Nn * Aa];     // centered s features
__device__ float g_AUG[Nn * Aa];   // augmented feature rows
__device__ float g_P[Nn * Cc];     // U @ W^T
__device__ float g_Y[Nn * Cc];     // AUG @ W^T + bias
__device__ float g_lossSum;
__device__ unsigned int g_done;

// ---------------------------------------------------------------------------
// K1: per-sample centering + augmented mean rows.
//   U[n]   = s[n] - mean_{m: ts[m]==ts[n]} s[m]
//   AUG[n] = 0.5*( meanS(tt[n]) [0 if empty] + meanT(tt[n]) )
// grid = N blocks, 256 threads
// ---------------------------------------------------------------------------
__global__ void center_aug_kernel(const float* __restrict__ s,
                                  const float* __restrict__ t,
                                  const int* __restrict__ ts,
                                  const int* __restrict__ tt) {
    __shared__ int sh_ts[Nn];
    __shared__ int listA[Nn], listS[Nn], listT[Nn];
    __shared__ int cA, cS, cT;

    const int n = blockIdx.x;
    const int tid = threadIdx.x;

    if (tid == 0) {
        cA = 0; cS = 0; cT = 0;
        if (n == 0) { g_lossSum = 0.0f; g_done = 0u; }
    }
    if (tid < Nn) sh_ts[tid] = ts[tid];
    __syncthreads();

    const int k1 = sh_ts[n];   // own s-class
    const int k2 = tt[n];      // target_t class
    if (tid < Nn) {
        const int tsm = sh_ts[tid];
        if (tsm == k1) listA[atomicAdd(&cA, 1)] = tid;
        if (tsm == k2) listS[atomicAdd(&cS, 1)] = tid;
        if (tt[tid] == k2) listT[atomicAdd(&cT, 1)] = tid;
    }
    __syncthreads();

    const int nA = cA, nS = cS, nT = cT;
    const float invA = 1.0f / (float)max(nA, 1);      // nA >= 1 (n itself)
    const float invS = (nS > 0) ? 1.0f / (float)nS : 0.0f;  // w_cv zeroing
    const float invT = 1.0f / (float)max(nT, 1);      // nT >= 1 (n itself)

    for (int a = tid; a < Aa; a += blockDim.x) {
        float sumA = 0.f, sumS = 0.f, sumT = 0.f;
        for (int j = 0; j < nA; ++j) sumA += s[listA[j] * Aa + a];
        for (int j = 0; j < nS; ++j) sumS += s[listS[j] * Aa + a];
        for (int j = 0; j < nT; ++j) sumT += t[listT[j] * Aa + a];
        g_U[n * Aa + a]   = s[n * Aa + a] - sumA * invA;
        g_AUG[n * Aa + a] = 0.5f * (sumS * invS + sumT * invT);
    }
}

// ---------------------------------------------------------------------------
// K2: two fused 128x256x512 fp32 GEMMs (NT: both operands K-contiguous).
//   z=0: P = U @ W[:C]^T       z=1: Y = AUG @ W[:C]^T + bias[:C]
// 32x32 output tile, BK=32, 256 threads, 4 outputs/thread.
// grid = (C/32, N/32, 2)
// ---------------------------------------------------------------------------
__global__ void gemm2_kernel(const float* __restrict__ W,
                             const float* __restrict__ bias) {
    __shared__ float Xs[32][33];
    __shared__ float Ws[32][33];

    const float* X = (blockIdx.z == 0) ? g_U : g_AUG;
    float*       O = (blockIdx.z == 0) ? g_P : g_Y;

    const int c0 = blockIdx.x * 32;
    const int m0 = blockIdx.y * 32;
    const int tid = threadIdx.x;
    const int tx = tid & 31;       // output col within tile
    const int ty = tid >> 5;       // output row group (0..7)

    float acc0 = 0.f, acc1 = 0.f, acc2 = 0.f, acc3 = 0.f;

    for (int k0 = 0; k0 < Aa; k0 += 32) {
#pragma unroll
        for (int i = 0; i < 4; ++i) {
            const int idx = tid + i * 256;
            const int r = idx >> 5, k = idx & 31;
            Xs[r][k] = X[(m0 + r) * Aa + k0 + k];
            Ws[r][k] = W[(c0 + r) * Aa + k0 + k];
        }
        __syncthreads();
#pragma unroll
        for (int k = 0; k < 32; ++k) {
            const float wv = Ws[tx][k];
            acc0 += Xs[ty +  0][k] * wv;
            acc1 += Xs[ty +  8][k] * wv;
            acc2 += Xs[ty + 16][k] * wv;
            acc3 += Xs[ty + 24][k] * wv;
        }
        __syncthreads();
    }

    const float b = (blockIdx.z == 1) ? bias[c0 + tx] : 0.0f;
    O[(m0 + ty +  0) * Cc + c0 + tx] = acc0 + b;
    O[(m0 + ty +  8) * Cc + c0 + tx] = acc1 + b;
    O[(m0 + ty + 16) * Cc + c0 + tx] = acc2 + b;
    O[(m0 + ty + 24) * Cc + c0 + tx] = acc3 + b;
}

// ---------------------------------------------------------------------------
// K3: sigma_diag add + log-softmax + NLL, mean via last-block-done.
// grid = N blocks, 256 threads (one per class c)
// ---------------------------------------------------------------------------
__global__ void sigma_loss_kernel(const int* __restrict__ ts,
                                  const int* __restrict__ tt,
                                  float* __restrict__ out) {
    __shared__ int   mlist[Nn];
    __shared__ float pk[Nn];
    __shared__ int   mcnt;
    __shared__ float red[8];
    __shared__ float sh_yk;

    const int n = blockIdx.x;
    const int tid = threadIdx.x;      // = class c
    const int k = tt[n];

    if (tid == 0) mcnt = 0;
    __syncthreads();
    if (tid < Nn && ts[tid] == k) mlist[atomicAdd(&mcnt, 1)] = tid;
    __syncthreads();
    const int cnt = mcnt;
    if (tid < cnt) pk[tid] = g_P[mlist[tid] * Cc + k];
    __syncthreads();

    const float inv = (cnt > 0) ? 1.0f / (float)cnt : 0.0f;

    float sig = 0.f;
    for (int j = 0; j < cnt; ++j) {
        const float d = g_P[mlist[j] * Cc + tid] - pk[j];
        sig += d * d;
    }
    float y = g_Y[n * Cc + tid] + 0.25f * sig * inv;   // 0.5*alpha = 0.25

    // block max
    float m = y;
#pragma unroll
    for (int o = 16; o; o >>= 1) m = fmaxf(m, __shfl_xor_sync(0xffffffffu, m, o));
    if ((tid & 31) == 0) red[tid >> 5] = m;
    __syncthreads();
    m = red[0];
#pragma unroll
    for (int w = 1; w < 8; ++w) m = fmaxf(m, red[w]);
    __syncthreads();

    // block sum of exp
    float e = __expf(y - m) ;
    // use accurate expf to stay close to reference
    e = expf(y - m);
#pragma unroll
    for (int o = 16; o; o >>= 1) e += __shfl_xor_sync(0xffffffffu, e, o);
    if ((tid & 31) == 0) red[tid >> 5] = e;
    if (tid == k) sh_yk = y;
    __syncthreads();
    float tot = 0.f;
#pragma unroll
    for (int w = 0; w < 8; ++w) tot += red[w];

    if (tid == 0) {
        const float loss_n = -(sh_yk - m - logf(tot));
        atomicAdd(&g_lossSum, loss_n);
        __threadfence();
        const unsigned int prev = atomicAdd(&g_done, 1u);
        if (prev == gridDim.x - 1) {
            const float total = atomicAdd(&g_lossSum, 0.0f);  // atomic read
            out[0] = total * (1.0f / (float)Nn);
        }
    }
}

// ---------------------------------------------------------------------------
extern "C" void kernel_launch(void* const* d_in, const int* in_sizes, int n_in,
                              void* d_out, int out_size) {
    const float* fc_weight = (const float*)d_in[0];   // (2C, A)
    const float* fc_bias   = (const float*)d_in[1];   // (2C,)
    const float* s_feat    = (const float*)d_in[2];   // (N, A)
    const float* t_feat    = (const float*)d_in[3];   // (N, A)
    const int*   target_s  = (const int*)d_in[4];     // (N,)
    const int*   target_t  = (const int*)d_in[5];     // (N,)
    float* out = (float*)d_out;

    center_aug_kernel<<<Nn, 256>>>(s_feat, t_feat, target_s, target_t);

    dim3 g(Cc / 32, Nn / 32, 2);
    gemm2_kernel<<<g, 256>>>(fc_weight, fc_bias);

    sigma_loss_kernel<<<Nn, 256>>>(target_s, target_t, out);
}

// round 3
// speedup vs baseline: 1.6379x; 1.6379x over previous
#include <cuda_runtime.h>
#include <math.h>

#define Nn 128
#define Cc 256
#define Aa 512
#define NB 128
#define NT 256

// Scratch (device globals — no allocations allowed)
__device__ float g_U[Nn * Aa];     // centered s features
__device__ float g_AUG[Nn * Aa];   // augmented feature rows
__device__ float g_P[Nn * Cc];     // U @ W^T
__device__ float g_Y[Nn * Cc];     // AUG @ W^T (bias added in phase 3)
__device__ float g_loss[Nn];       // per-sample loss
__device__ unsigned int g_barCount = 0;
__device__ unsigned int g_barGen = 0;

struct SmemP1 {
    int ts[Nn], tt[Nn];
    int listA[Nn], listS[Nn], listT[Nn];
    int wA[4], wS[4], wT[4];
};
struct SmemP2 {
    float Xs[32][34];   // k-major transposed X tile (pad 34 keeps float2 align + banks)
    float Ws[32][34];   // k-major transposed W tile
};
struct SmemP3 {
    int mlist[Nn];
    float pk[Nn];
    float red[8];
    float yk;
    int wcnt[4];
};
union __align__(16) SmemU { SmemP1 p1; SmemP2 p2; SmemP3 p3; };

// Grid-wide barrier: all NB blocks are co-resident (single wave), so a spin
// on a generation counter is deadlock-free and graph-capturable.
__device__ __forceinline__ void grid_barrier() {
    __threadfence();                 // publish this thread's writes device-wide
    __syncthreads();
    if (threadIdx.x == 0) {
        unsigned int gen = *(volatile unsigned int*)&g_barGen;
        unsigned int my = atomicAdd(&g_barCount, 1u);
        if (my == NB - 1u) {
            *(volatile unsigned int*)&g_barCount = 0u;
            __threadfence();
            atomicAdd(&g_barGen, 1u);
        } else {
            while (*(volatile unsigned int*)&g_barGen == gen) __nanosleep(64);
        }
        __threadfence();
    }
    __syncthreads();
}

__global__ __launch_bounds__(NT, 1)
void isda_fused_kernel(const float* __restrict__ W,
                       const float* __restrict__ bias,
                       const float* __restrict__ s,
                       const float* __restrict__ t,
                       const int* __restrict__ ts,
                       const int* __restrict__ tt,
                       float* __restrict__ out)
{
    __shared__ SmemU sm;
    const int tid  = threadIdx.x;
    const int bid  = blockIdx.x;
    const int lane = tid & 31;
    const int warp = tid >> 5;

    // ================= Phase 1: centering + augmented rows ==================
    {
        const int n = bid;
        if (tid < Nn) { sm.p1.ts[tid] = ts[tid]; sm.p1.tt[tid] = tt[tid]; }
        __syncthreads();
        const int k1 = sm.p1.ts[n];
        const int k2 = sm.p1.tt[n];

        const bool valid = tid < Nn;
        const bool pA = valid && (sm.p1.ts[tid] == k1);
        const bool pS = valid && (sm.p1.ts[tid] == k2);
        const bool pT = valid && (sm.p1.tt[tid] == k2);
        const unsigned mA = __ballot_sync(0xffffffffu, pA);
        const unsigned mS = __ballot_sync(0xffffffffu, pS);
        const unsigned mT = __ballot_sync(0xffffffffu, pT);
        if (lane == 0 && warp < 4) {
            sm.p1.wA[warp] = __popc(mA);
            sm.p1.wS[warp] = __popc(mS);
            sm.p1.wT[warp] = __popc(mT);
        }
        __syncthreads();
        const unsigned lt = (1u << lane) - 1u;
        if (warp < 4) {
            int bA = 0, bS = 0, bT = 0;
#pragma unroll
            for (int w = 0; w < 4; ++w) {
                if (w < warp) { bA += sm.p1.wA[w]; bS += sm.p1.wS[w]; bT += sm.p1.wT[w]; }
            }
            if (pA) sm.p1.listA[bA + __popc(mA & lt)] = tid;
            if (pS) sm.p1.listS[bS + __popc(mS & lt)] = tid;
            if (pT) sm.p1.listT[bT + __popc(mT & lt)] = tid;
        }
        const int nA = sm.p1.wA[0] + sm.p1.wA[1] + sm.p1.wA[2] + sm.p1.wA[3];
        const int nS = sm.p1.wS[0] + sm.p1.wS[1] + sm.p1.wS[2] + sm.p1.wS[3];
        const int nT = sm.p1.wT[0] + sm.p1.wT[1] + sm.p1.wT[2] + sm.p1.wT[3];

        // zero this block's P/Y rows (phase 2 accumulates with atomics)
        g_P[n * Cc + tid] = 0.0f;
        g_Y[n * Cc + tid] = 0.0f;
        __syncthreads();

        if (tid < 128) {
            // U[n] = s[n] - classmean_s(ts[n])
            const int a4 = tid;
            const float4 me = ((const float4*)(s + (size_t)n * Aa))[a4];
            float sx = 0.f, sy = 0.f, sz = 0.f, sw = 0.f;
#pragma unroll 4
            for (int j = 0; j < nA; ++j) {
                const float4 v = ((const float4*)(s + (size_t)sm.p1.listA[j] * Aa))[a4];
                sx += v.x; sy += v.y; sz += v.z; sw += v.w;
            }
            const float invA = 1.0f / (float)nA;   // nA >= 1 (n itself)
            float4 u;
            u.x = me.x - sx * invA; u.y = me.y - sy * invA;
            u.z = me.z - sz * invA; u.w = me.w - sw * invA;
            ((float4*)(g_U + (size_t)n * Aa))[a4] = u;
        } else {
            // AUG[n] = 0.5*( meanS(tt[n]) [0 if empty] + meanT(tt[n]) )
            const int a4 = tid - 128;
            float ax = 0.f, ay = 0.f, az = 0.f, aw = 0.f;
#pragma unroll 4
            for (int j = 0; j < nS; ++j) {
                const float4 v = ((const float4*)(s + (size_t)sm.p1.listS[j] * Aa))[a4];
                ax += v.x; ay += v.y; az += v.z; aw += v.w;
            }
            float bx = 0.f, by = 0.f, bz = 0.f, bw = 0.f;
#pragma unroll 4
            for (int j = 0; j < nT; ++j) {
                const float4 v = ((const float4*)(t + (size_t)sm.p1.listT[j] * Aa))[a4];
                bx += v.x; by += v.y; bz += v.z; bw += v.w;
            }
            const float invS = (nS > 0) ? 1.0f / (float)nS : 0.0f;  // w_cv zeroing
            const float invT = 1.0f / (float)nT;                    // nT >= 1
            float4 g;
            g.x = 0.5f * (ax * invS + bx * invT);
            g.y = 0.5f * (ay * invS + by * invT);
            g.z = 0.5f * (az * invS + bz * invT);
            g.w = 0.5f * (aw * invS + bw * invT);
            ((float4*)(g_AUG + (size_t)n * Aa))[a4] = g;
        }
    }
    grid_barrier();

    // ================= Phase 2: two GEMMs, 128-block decomposition ==========
    // bid bits: mt[1:0] (M/32), ct[4:2] (C/32), zz[5] (P vs Y), kh[6] (K half)
    {
        const int mt = bid & 3;
        const int ct = (bid >> 2) & 7;
        const int zz = (bid >> 5) & 1;
        const int kh = (bid >> 6) & 1;
        const int m0 = mt * 32, c0 = ct * 32, kb = kh * 256;
        const float* X = zz ? g_AUG : g_U;
        float*       O = zz ? g_Y  : g_P;

        const int c2 = tid & 15;   // c pair index -> cols {2c2, 2c2+1}
        const int m2 = tid >> 4;   // m pair index -> rows {2m2, 2m2+1}
        float a00 = 0.f, a01 = 0.f, a10 = 0.f, a11 = 0.f;

        for (int kc = 0; kc < 256; kc += 32) {
#pragma unroll
            for (int i = 0; i < 4; ++i) {
                const int idx = tid + i * 256;   // 0..1023
                const int r  = idx >> 5;         // 0..31 (m or c row)
                const int kk = idx & 31;
                sm.p2.Xs[kk][r] = X[(size_t)(m0 + r) * Aa + kb + kc + kk];
                sm.p2.Ws[kk][r] = W[(size_t)(c0 + r) * Aa + kb + kc + kk];
            }
            __syncthreads();
#pragma unroll
            for (int kk = 0; kk < 32; ++kk) {
                const float2 wv = *(const float2*)&sm.p2.Ws[kk][2 * c2];
                const float2 xv = *(const float2*)&sm.p2.Xs[kk][2 * m2];
                a00 += xv.x * wv.x; a01 += xv.x * wv.y;
                a10 += xv.y * wv.x; a11 += xv.y * wv.y;
            }
            __syncthreads();
        }
        float* o0 = O + (size_t)(m0 + 2 * m2) * Cc + c0 + 2 * c2;
        atomicAdd(o0 + 0,      a00); atomicAdd(o0 + 1,      a01);
        atomicAdd(o0 + Cc + 0, a10); atomicAdd(o0 + Cc + 1, a11);
    }
    grid_barrier();

    // ================= Phase 3: sigma + log-softmax + NLL ===================
    {
        const int n = bid;
        const int k = tt[n];
        const bool valid = tid < Nn;
        const bool pM = valid && (ts[tid] == k);
        const unsigned mM = __ballot_sync(0xffffffffu, pM);
        if (lane == 0 && warp < 4) sm.p3.wcnt[warp] = __popc(mM);
        __syncthreads();
        if (warp < 4) {
            int base = 0;
#pragma unroll
            for (int w = 0; w < 4; ++w) if (w < warp) base += sm.p3.wcnt[w];
            if (pM) sm.p3.mlist[base + __popc(mM & ((1u << lane) - 1u))] = tid;
        }
        const int cnt = sm.p3.wcnt[0] + sm.p3.wcnt[1] + sm.p3.wcnt[2] + sm.p3.wcnt[3];
        __syncthreads();
        if (tid < cnt) sm.p3.pk[tid] = g_P[(size_t)sm.p3.mlist[tid] * Cc + k];
        __syncthreads();

        const float inv = (cnt > 0) ? 1.0f / (float)cnt : 0.0f;
        float sig = 0.f;
        for (int j = 0; j < cnt; ++j) {
            const float d = g_P[(size_t)sm.p3.mlist[j] * Cc + tid] - sm.p3.pk[j];
            sig += d * d;
        }
        float y = g_Y[(size_t)n * Cc + tid] + bias[tid] + 0.25f * sig * inv;  // 0.5*alpha

        // block max
        float mmax = y;
#pragma unroll
        for (int o = 16; o; o >>= 1) mmax = fmaxf(mmax, __shfl_xor_sync(0xffffffffu, mmax, o));
        if (lane == 0) sm.p3.red[warp] = mmax;
        __syncthreads();
        mmax = sm.p3.red[0];
#pragma unroll
        for (int w = 1; w < 8; ++w) mmax = fmaxf(mmax, sm.p3.red[w]);
        __syncthreads();

        // block sum of exp
        float e = expf(y - mmax);
#pragma unroll
        for (int o = 16; o; o >>= 1) e += __shfl_xor_sync(0xffffffffu, e, o);
        if (lane == 0) sm.p3.red[warp] = e;
        if (tid == k) sm.p3.yk = y;
        __syncthreads();
        if (tid == 0) {
            float tot = 0.f;
#pragma unroll
            for (int w = 0; w < 8; ++w) tot += sm.p3.red[w];
            g_loss[n] = -(sm.p3.yk - mmax - logf(tot));
        }
    }
    grid_barrier();

    // ================= Phase 4: deterministic mean on block 0 ===============
    if (bid == 0) {
        float v = (tid < Nn) ? g_loss[tid] : 0.0f;
#pragma unroll
        for (int o = 16; o; o >>= 1) v += __shfl_xor_sync(0xffffffffu, v, o);
        if (lane == 0) sm.p3.red[warp] = v;
        __syncthreads();
        if (tid == 0) {
            float tot = 0.f;
#pragma unroll
            for (int w = 0; w < 8; ++w) tot += sm.p3.red[w];
            out[0] = tot * (1.0f / (float)Nn);
        }
    }
}

// ---------------------------------------------------------------------------
extern "C" void kernel_launch(void* const* d_in, const int* in_sizes, int n_in,
                              void* d_out, int out_size) {
    const float* fc_weight = (const float*)d_in[0];   // (2C, A)
    const float* fc_bias   = (const float*)d_in[1];   // (2C,)
    const float* s_feat    = (const float*)d_in[2];   // (N, A)
    const float* t_feat    = (const float*)d_in[3];   // (N, A)
    const int*   target_s  = (const int*)d_in[4];     // (N,)
    const int*   target_t  = (const int*)d_in[5];     // (N,)
    float* out = (float*)d_out;

    isda_fused_kernel<<<NB, NT>>>(fc_weight, fc_bias, s_feat, t_feat,
                                  target_s, target_t, out);
}

// round 4
// speedup vs baseline: 2.0069x; 1.2253x over previous
#include <cuda_runtime.h>
#include <math.h>

#define Nn 128
#define Cc 256
#define Aa 512
#define NB 128
#define NT 256
#define KSPLIT 8           // K-chunks of 64
#define TSTRIDE 66         // smem row stride (floats): 8B-aligned, conflict-free

// Scratch (device globals — no allocations allowed)
__device__ float g_X[2 * Nn * Aa];             // rows 0..127: U, 128..255: AUG
__device__ float g_part[KSPLIT * 2 * Nn * Cc]; // K-split partial outputs (2 MB)
__device__ float g_loss[Nn];
__device__ unsigned int g_barCount = 0;
__device__ unsigned int g_barGen = 0;

struct SmemP1 {
    int ts[Nn], tt[Nn];
    int listA[Nn], listS[Nn], listT[Nn];
    int wA[4], wS[4], wT[4];
};
struct SmemP2 {
    float Xs[64][TSTRIDE];
    float Ws[64][TSTRIDE];
};
struct SmemP3 {
    int mlist[Nn];
    float pk[Nn];
    float red[8];
    float yk;
    int wcnt[4];
};
union __align__(16) SmemU { SmemP1 p1; SmemP2 p2; SmemP3 p3; };

// Grid-wide barrier: all NB blocks co-resident (single wave, NB <= #SMs).
__device__ __forceinline__ void grid_barrier() {
    __threadfence();
    __syncthreads();
    if (threadIdx.x == 0) {
        unsigned int gen = *(volatile unsigned int*)&g_barGen;
        unsigned int my = atomicAdd(&g_barCount, 1u);
        if (my == NB - 1u) {
            *(volatile unsigned int*)&g_barCount = 0u;
            __threadfence();
            atomicAdd(&g_barGen, 1u);
        } else {
            while (*(volatile unsigned int*)&g_barGen == gen) __nanosleep(32);
        }
        __threadfence();
    }
    __syncthreads();
}

__global__ __launch_bounds__(NT, 1)
void isda_fused_kernel(const float* __restrict__ W,
                       const float* __restrict__ bias,
                       const float* __restrict__ s,
                       const float* __restrict__ t,
                       const int* __restrict__ ts,
                       const int* __restrict__ tt,
                       float* __restrict__ out)
{
    __shared__ SmemU sm;
    const int tid  = threadIdx.x;
    const int bid  = blockIdx.x;
    const int lane = tid & 31;
    const int warp = tid >> 5;

    // ================= Phase 1: centering + augmented rows ==================
    {
        const int n = bid;
        if (tid < Nn) { sm.p1.ts[tid] = ts[tid]; sm.p1.tt[tid] = tt[tid]; }
        __syncthreads();
        const int k1 = sm.p1.ts[n];
        const int k2 = sm.p1.tt[n];

        const bool valid = tid < Nn;
        const bool pA = valid && (sm.p1.ts[tid] == k1);
        const bool pS = valid && (sm.p1.ts[tid] == k2);
        const bool pT = valid && (sm.p1.tt[tid] == k2);
        const unsigned mA = __ballot_sync(0xffffffffu, pA);
        const unsigned mS = __ballot_sync(0xffffffffu, pS);
        const unsigned mT = __ballot_sync(0xffffffffu, pT);
        if (lane == 0 && warp < 4) {
            sm.p1.wA[warp] = __popc(mA);
            sm.p1.wS[warp] = __popc(mS);
            sm.p1.wT[warp] = __popc(mT);
        }
        __syncthreads();
        const unsigned lt = (1u << lane) - 1u;
        if (warp < 4) {
            int bA = 0, bS = 0, bT = 0;
#pragma unroll
            for (int w = 0; w < 4; ++w)
                if (w < warp) { bA += sm.p1.wA[w]; bS += sm.p1.wS[w]; bT += sm.p1.wT[w]; }
            if (pA) sm.p1.listA[bA + __popc(mA & lt)] = tid;
            if (pS) sm.p1.listS[bS + __popc(mS & lt)] = tid;
            if (pT) sm.p1.listT[bT + __popc(mT & lt)] = tid;
        }
        const int nA = sm.p1.wA[0] + sm.p1.wA[1] + sm.p1.wA[2] + sm.p1.wA[3];
        const int nS = sm.p1.wS[0] + sm.p1.wS[1] + sm.p1.wS[2] + sm.p1.wS[3];
        const int nT = sm.p1.wT[0] + sm.p1.wT[1] + sm.p1.wT[2] + sm.p1.wT[3];
        __syncthreads();

        if (tid < 128) {
            // X[row n] = U[n] = s[n] - classmean_s(ts[n])
            const int a4 = tid;
            const float4 me = ((const float4*)(s + (size_t)n * Aa))[a4];
            float sx = 0.f, sy = 0.f, sz = 0.f, sw = 0.f;
#pragma unroll 4
            for (int j = 0; j < nA; ++j) {
                const float4 v = ((const float4*)(s + (size_t)sm.p1.listA[j] * Aa))[a4];
                sx += v.x; sy += v.y; sz += v.z; sw += v.w;
            }
            const float invA = 1.0f / (float)nA;   // nA >= 1 (n itself)
            float4 u;
            u.x = me.x - sx * invA; u.y = me.y - sy * invA;
            u.z = me.z - sz * invA; u.w = me.w - sw * invA;
            ((float4*)(g_X + (size_t)n * Aa))[a4] = u;
        } else {
            // X[row 128+n] = AUG[n] = 0.5*( meanS(tt[n]) [0 if empty] + meanT(tt[n]) )
            const int a4 = tid - 128;
            float ax = 0.f, ay = 0.f, az = 0.f, aw = 0.f;
#pragma unroll 4
            for (int j = 0; j < nS; ++j) {
                const float4 v = ((const float4*)(s + (size_t)sm.p1.listS[j] * Aa))[a4];
                ax += v.x; ay += v.y; az += v.z; aw += v.w;
            }
            float bx = 0.f, by = 0.f, bz = 0.f, bw = 0.f;
#pragma unroll 4
            for (int j = 0; j < nT; ++j) {
                const float4 v = ((const float4*)(t + (size_t)sm.p1.listT[j] * Aa))[a4];
                bx += v.x; by += v.y; bz += v.z; bw += v.w;
            }
            const float invS = (nS > 0) ? 1.0f / (float)nS : 0.0f;  // w_cv zeroing
            const float invT = 1.0f / (float)nT;                    // nT >= 1
            float4 g;
            g.x = 0.5f * (ax * invS + bx * invT);
            g.y = 0.5f * (ay * invS + by * invT);
            g.z = 0.5f * (az * invS + bz * invT);
            g.w = 0.5f * (aw * invS + bw * invT);
            ((float4*)(g_X + (size_t)(Nn + n) * Aa))[a4] = g;
        }
    }
    grid_barrier();

    // ====== Phase 2: 256x256x512 GEMM, 64x64 tiles, 8-way K-split ==========
    // bid = mt*32? No: bid bits: [1:0]=mt (M/64), [3:2]=ct (C/64), [6:4]=kt
    {
        const int mt = bid & 3;
        const int ct = (bid >> 2) & 3;
        const int kt = bid >> 4;          // 0..7
        const int m0 = mt * 64, c0 = ct * 64, kb = kt * 64;

        // Stage both 64x64 tiles (row-major, stride TSTRIDE) in one shot.
        float4 xr[4], wr[4];
#pragma unroll
        for (int i = 0; i < 4; ++i) {
            const int idx = tid + i * 256;
            const int r = idx >> 4, kq = idx & 15;
            xr[i] = *(const float4*)&g_X[(size_t)(m0 + r) * Aa + kb + kq * 4];
            wr[i] = *(const float4*)&W  [(size_t)(c0 + r) * Aa + kb + kq * 4];
        }
#pragma unroll
        for (int i = 0; i < 4; ++i) {
            const int idx = tid + i * 256;
            const int r = idx >> 4, kq = idx & 15;
            *(float2*)&sm.p2.Xs[r][kq * 4]     = make_float2(xr[i].x, xr[i].y);
            *(float2*)&sm.p2.Xs[r][kq * 4 + 2] = make_float2(xr[i].z, xr[i].w);
            *(float2*)&sm.p2.Ws[r][kq * 4]     = make_float2(wr[i].x, wr[i].y);
            *(float2*)&sm.p2.Ws[r][kq * 4 + 2] = make_float2(wr[i].z, wr[i].w);
        }
        __syncthreads();

        const int tx = tid & 15;          // c sub-index
        const int ty = tid >> 4;          // m sub-index
        float acc[16];
#pragma unroll
        for (int i = 0; i < 16; ++i) acc[i] = 0.f;

#pragma unroll 4
        for (int kk = 0; kk < 64; kk += 2) {
            float2 xv[4], wv[4];
#pragma unroll
            for (int i = 0; i < 4; ++i) xv[i] = *(const float2*)&sm.p2.Xs[ty + 16 * i][kk];
#pragma unroll
            for (int u = 0; u < 4; ++u) wv[u] = *(const float2*)&sm.p2.Ws[tx + 16 * u][kk];
#pragma unroll
            for (int i = 0; i < 4; ++i)
#pragma unroll
                for (int u = 0; u < 4; ++u)
                    acc[i * 4 + u] += xv[i].x * wv[u].x + xv[i].y * wv[u].y;
        }

        float* base = g_part + (size_t)kt * (2 * Nn * Cc);
#pragma unroll
        for (int i = 0; i < 4; ++i)
#pragma unroll
            for (int u = 0; u < 4; ++u)
                base[(size_t)(m0 + ty + 16 * i) * Cc + c0 + tx + 16 * u] = acc[i * 4 + u];
    }
    grid_barrier();

    // ================= Phase 3: sigma + log-softmax + NLL ===================
    {
        const int n = bid;
        const int k = tt[n];
        const bool valid = tid < Nn;
        const bool pM = valid && (ts[tid] == k);
        const unsigned mM = __ballot_sync(0xffffffffu, pM);
        if (lane == 0 && warp < 4) sm.p3.wcnt[warp] = __popc(mM);
        __syncthreads();
        if (warp < 4) {
            int base = 0;
#pragma unroll
            for (int w = 0; w < 4; ++w) if (w < warp) base += sm.p3.wcnt[w];
            if (pM) sm.p3.mlist[base + __popc(mM & ((1u << lane) - 1u))] = tid;
        }
        const int cnt = sm.p3.wcnt[0] + sm.p3.wcnt[1] + sm.p3.wcnt[2] + sm.p3.wcnt[3];
        __syncthreads();
        if (tid < cnt) {
            const int m = sm.p3.mlist[tid];
            float p = 0.f;
#pragma unroll
            for (int q = 0; q < KSPLIT; ++q)
                p += g_part[(size_t)q * (2 * Nn * Cc) + (size_t)m * Cc + k];
            sm.p3.pk[tid] = p;
        }
        __syncthreads();

        const float inv = (cnt > 0) ? 1.0f / (float)cnt : 0.0f;
        float sig = 0.f;
        for (int j = 0; j < cnt; ++j) {
            const int m = sm.p3.mlist[j];
            float p = 0.f;
#pragma unroll
            for (int q = 0; q < KSPLIT; ++q)
                p += g_part[(size_t)q * (2 * Nn * Cc) + (size_t)m * Cc + tid];
            const float d = p - sm.p3.pk[j];
            sig += d * d;
        }
        float y = bias[tid] + 0.25f * sig * inv;   // 0.5 * alpha
#pragma unroll
        for (int q = 0; q < KSPLIT; ++q)
            y += g_part[(size_t)q * (2 * Nn * Cc) + (size_t)(Nn + n) * Cc + tid];

        // block max
        float mmax = y;
#pragma unroll
        for (int o = 16; o; o >>= 1) mmax = fmaxf(mmax, __shfl_xor_sync(0xffffffffu, mmax, o));
        if (lane == 0) sm.p3.red[warp] = mmax;
        __syncthreads();
        mmax = sm.p3.red[0];
#pragma unroll
        for (int w = 1; w < 8; ++w) mmax = fmaxf(mmax, sm.p3.red[w]);
        __syncthreads();

        float e = expf(y - mmax);
#pragma unroll
        for (int o = 16; o; o >>= 1) e += __shfl_xor_sync(0xffffffffu, e, o);
        if (lane == 0) sm.p3.red[warp] = e;
        if (tid == k) sm.p3.yk = y;
        __syncthreads();
        if (tid == 0) {
            float tot = 0.f;
#pragma unroll
            for (int w = 0; w < 8; ++w) tot += sm.p3.red[w];
            g_loss[n] = -(sm.p3.yk - mmax - logf(tot));
        }
    }
    grid_barrier();

    // ================= Phase 4: deterministic mean on block 0 ===============
    if (bid == 0) {
        float v = (tid < Nn) ? g_loss[tid] : 0.0f;
#pragma unroll
        for (int o = 16; o; o >>= 1) v += __shfl_xor_sync(0xffffffffu, v, o);
        if (lane == 0) sm.p3.red[warp] = v;
        __syncthreads();
        if (tid == 0) {
            float tot = 0.f;
#pragma unroll
            for (int w = 0; w < 8; ++w) tot += sm.p3.red[w];
            out[0] = tot * (1.0f / (float)Nn);
        }
    }
}

// ---------------------------------------------------------------------------
extern "C" void kernel_launch(void* const* d_in, const int* in_sizes, int n_in,
                              void* d_out, int out_size) {
    const float* fc_weight = (const float*)d_in[0];   // (2C, A)
    const float* fc_bias   = (const float*)d_in[1];   // (2C,)
    const float* s_feat    = (const float*)d_in[2];   // (N, A)
    const float* t_feat    = (const float*)d_in[3];   // (N, A)
    const int*   target_s  = (const int*)d_in[4];     // (N,)
    const int*   target_t  = (const int*)d_in[5];     // (N,)
    float* out = (float*)d_out;

    isda_fused_kernel<<<NB, NT>>>(fc_weight, fc_bias, s_feat, t_feat,
                                  target_s, target_t, out);
}

// round 5
// speedup vs baseline: 2.0568x; 1.0249x over previous
#include <cuda_runtime.h>
#include <math.h>

#define Nn 128
#define Cc 256
#define Aa 512
#define NB 128
#define NT 256
#define KSPLIT 8           // K-chunks of 64
#define TS 66              // smem row stride (floats): even (8B-aligned rows)

// Scratch (device globals — no allocations allowed)
__device__ float g_X[2 * Nn * Aa];             // rows 0..127: U, 128..255: AUG
__device__ float g_part[KSPLIT * 2 * Nn * Cc]; // K-split partial outputs (2 MB)
__device__ float g_lossSum;
__device__ unsigned int g_doneCnt;
__device__ unsigned int g_barCount = 0;
__device__ unsigned int g_barGen = 0;

struct SmemP1 {
    int ts[Nn], tt[Nn];
    int listA[Nn], listS[Nn], listT[Nn];
    int wA[4], wS[4], wT[4];
};
struct SmemP2 { float Xs[64][TS]; };
struct SmemP3 {
    int mlist[Nn];
    float pk[Nn];
    float red[8];
    float yk;
    int wcnt[4];
};
union __align__(16) SmemU { SmemP1 p1; SmemP2 p2; SmemP3 p3; };

// Grid-wide barrier: all NB blocks co-resident (single wave, NB <= #SMs).
__device__ __forceinline__ void grid_barrier() {
    __threadfence();
    __syncthreads();
    if (threadIdx.x == 0) {
        unsigned int gen = *(volatile unsigned int*)&g_barGen;
        unsigned int my = atomicAdd(&g_barCount, 1u);
        if (my == NB - 1u) {
            *(volatile unsigned int*)&g_barCount = 0u;
            __threadfence();
            atomicAdd(&g_barGen, 1u);
        } else {
            while (*(volatile unsigned int*)&g_barGen == gen) __nanosleep(32);
        }
        __threadfence();
    }
    __syncthreads();
}

__global__ __launch_bounds__(NT, 1)
void isda_fused_kernel(const float* __restrict__ W,
                       const float* __restrict__ bias,
                       const float* __restrict__ s,
                       const float* __restrict__ t,
                       const int* __restrict__ ts,
                       const int* __restrict__ tt,
                       float* __restrict__ out)
{
    __shared__ SmemU sm;
    __shared__ float Wsm[64][TS];   // dedicated: prefetch overlaps phase 1
    const int tid  = threadIdx.x;
    const int bid  = blockIdx.x;
    const int lane = tid & 31;
    const int warp = tid >> 5;

    // Phase-2 tile coordinates (known immediately)
    const int mt = bid & 3;
    const int ct = (bid >> 2) & 3;
    const int kt = bid >> 4;                 // 0..7
    const int m0 = mt * 64, c0 = ct * 64, kb = kt * 64;

    // ---- Prefetch W tile (independent of phase 1): issue loads NOW ----
    float4 wr[4];
#pragma unroll
    for (int i = 0; i < 4; ++i) {
        const int idx = tid + i * 256;
        const int r = idx >> 4, kq = idx & 15;
        wr[i] = *(const float4*)&W[(size_t)(c0 + r) * Aa + kb + kq * 4];
    }

    // ================= Phase 1: centering + augmented rows ==================
    {
        const int n = bid;
        if (tid < Nn) { sm.p1.ts[tid] = ts[tid]; sm.p1.tt[tid] = tt[tid]; }
        if (tid == 0 && bid == 0) { g_lossSum = 0.0f; g_doneCnt = 0u; }
        __syncthreads();
        const int k1 = sm.p1.ts[n];
        const int k2 = sm.p1.tt[n];

        const bool valid = tid < Nn;
        const bool pA = valid && (sm.p1.ts[tid] == k1);
        const bool pS = valid && (sm.p1.ts[tid] == k2);
        const bool pT = valid && (sm.p1.tt[tid] == k2);
        const unsigned mA = __ballot_sync(0xffffffffu, pA);
        const unsigned mS = __ballot_sync(0xffffffffu, pS);
        const unsigned mT = __ballot_sync(0xffffffffu, pT);
        if (lane == 0 && warp < 4) {
            sm.p1.wA[warp] = __popc(mA);
            sm.p1.wS[warp] = __popc(mS);
            sm.p1.wT[warp] = __popc(mT);
        }
        __syncthreads();
        const unsigned lt = (1u << lane) - 1u;
        if (warp < 4) {
            int bA = 0, bS = 0, bT = 0;
#pragma unroll
            for (int w = 0; w < 4; ++w)
                if (w < warp) { bA += sm.p1.wA[w]; bS += sm.p1.wS[w]; bT += sm.p1.wT[w]; }
            if (pA) sm.p1.listA[bA + __popc(mA & lt)] = tid;
            if (pS) sm.p1.listS[bS + __popc(mS & lt)] = tid;
            if (pT) sm.p1.listT[bT + __popc(mT & lt)] = tid;
        }
        const int nA = sm.p1.wA[0] + sm.p1.wA[1] + sm.p1.wA[2] + sm.p1.wA[3];
        const int nS = sm.p1.wS[0] + sm.p1.wS[1] + sm.p1.wS[2] + sm.p1.wS[3];
        const int nT = sm.p1.wT[0] + sm.p1.wT[1] + sm.p1.wT[2] + sm.p1.wT[3];
        __syncthreads();

        if (tid < 128) {
            // X[row n] = U[n] = s[n] - classmean_s(ts[n])
            const int a4 = tid;
            const float4 me = ((const float4*)(s + (size_t)n * Aa))[a4];
            float sx = 0.f, sy = 0.f, sz = 0.f, sw = 0.f;
#pragma unroll 4
            for (int j = 0; j < nA; ++j) {
                const float4 v = ((const float4*)(s + (size_t)sm.p1.listA[j] * Aa))[a4];
                sx += v.x; sy += v.y; sz += v.z; sw += v.w;
            }
            const float invA = 1.0f / (float)nA;   // nA >= 1 (n itself)
            float4 u;
            u.x = me.x - sx * invA; u.y = me.y - sy * invA;
            u.z = me.z - sz * invA; u.w = me.w - sw * invA;
            ((float4*)(g_X + (size_t)n * Aa))[a4] = u;
        } else {
            // X[row 128+n] = AUG[n] = 0.5*( meanS(tt[n]) [0 if empty] + meanT(tt[n]) )
            const int a4 = tid - 128;
            float ax = 0.f, ay = 0.f, az = 0.f, aw = 0.f;
#pragma unroll 4
            for (int j = 0; j < nS; ++j) {
                const float4 v = ((const float4*)(s + (size_t)sm.p1.listS[j] * Aa))[a4];
                ax += v.x; ay += v.y; az += v.z; aw += v.w;
            }
            float bx = 0.f, by = 0.f, bz = 0.f, bw = 0.f;
#pragma unroll 4
            for (int j = 0; j < nT; ++j) {
                const float4 v = ((const float4*)(t + (size_t)sm.p1.listT[j] * Aa))[a4];
                bx += v.x; by += v.y; bz += v.z; bw += v.w;
            }
            const float invS = (nS > 0) ? 1.0f / (float)nS : 0.0f;  // w_cv zeroing
            const float invT = 1.0f / (float)nT;                    // nT >= 1
            float4 g;
            g.x = 0.5f * (ax * invS + bx * invT);
            g.y = 0.5f * (ay * invS + by * invT);
            g.z = 0.5f * (az * invS + bz * invT);
            g.w = 0.5f * (aw * invS + bw * invT);
            ((float4*)(g_X + (size_t)(Nn + n) * Aa))[a4] = g;
        }
    }

    // Park prefetched W tile into its smem (loads have had ~all of P1 to land)
#pragma unroll
    for (int i = 0; i < 4; ++i) {
        const int idx = tid + i * 256;
        const int r = idx >> 4, kq = idx & 15;
        *(float2*)&Wsm[r][kq * 4]     = make_float2(wr[i].x, wr[i].y);
        *(float2*)&Wsm[r][kq * 4 + 2] = make_float2(wr[i].z, wr[i].w);
    }
    grid_barrier();

    // ====== Phase 2: 256x256x512 GEMM, 64x64 tiles, 8-way K-split ==========
    {
        // Stage X tile
#pragma unroll
        for (int i = 0; i < 4; ++i) {
            const int idx = tid + i * 256;
            const int r = idx >> 4, kq = idx & 15;
            const float4 v = *(const float4*)&g_X[(size_t)(m0 + r) * Aa + kb + kq * 4];
            *(float2*)&sm.p2.Xs[r][kq * 4]     = make_float2(v.x, v.y);
            *(float2*)&sm.p2.Xs[r][kq * 4 + 2] = make_float2(v.z, v.w);
        }
        __syncthreads();

        const int tx = tid & 15;          // c sub-index
        const int ty = tid >> 4;          // m sub-index
        // f32x2 accumulators: lanes hold even-k / odd-k partial sums
        unsigned long long acc[16];
#pragma unroll
        for (int i = 0; i < 16; ++i) acc[i] = 0ull;

#pragma unroll 4
        for (int kk = 0; kk < 64; kk += 2) {
            unsigned long long xv[4], wv[4];
#pragma unroll
            for (int i = 0; i < 4; ++i)
                xv[i] = *(const unsigned long long*)&sm.p2.Xs[ty + 16 * i][kk];
#pragma unroll
            for (int u = 0; u < 4; ++u)
                wv[u] = *(const unsigned long long*)&Wsm[tx + 16 * u][kk];
#pragma unroll
            for (int i = 0; i < 4; ++i)
#pragma unroll
                for (int u = 0; u < 4; ++u)
                    asm("fma.rn.f32x2 %0, %1, %2, %0;"
                        : "+l"(acc[i * 4 + u]) : "l"(xv[i]), "l"(wv[u]));
        }

        float* base = g_part + (size_t)kt * (2 * Nn * Cc);
#pragma unroll
        for (int i = 0; i < 4; ++i)
#pragma unroll
            for (int u = 0; u < 4; ++u) {
                const unsigned long long a = acc[i * 4 + u];
                const float lo = __uint_as_float((unsigned int)(a & 0xffffffffull));
                const float hi = __uint_as_float((unsigned int)(a >> 32));
                base[(size_t)(m0 + ty + 16 * i) * Cc + c0 + tx + 16 * u] = lo + hi;
            }
    }
    grid_barrier();

    // ========= Phase 3: sigma + log-softmax + NLL + last-block mean =========
    {
        const int n = bid;
        const int k = tt[n];
        const bool valid = tid < Nn;
        const bool pM = valid && (ts[tid] == k);
        const unsigned mM = __ballot_sync(0xffffffffu, pM);
        if (lane == 0 && warp < 4) sm.p3.wcnt[warp] = __popc(mM);
        __syncthreads();
        if (warp < 4) {
            int base = 0;
#pragma unroll
            for (int w = 0; w < 4; ++w) if (w < warp) base += sm.p3.wcnt[w];
            if (pM) sm.p3.mlist[base + __popc(mM & ((1u << lane) - 1u))] = tid;
        }
        const int cnt = sm.p3.wcnt[0] + sm.p3.wcnt[1] + sm.p3.wcnt[2] + sm.p3.wcnt[3];
        __syncthreads();
        if (tid < cnt) {
            const int m = sm.p3.mlist[tid];
            float p = 0.f;
#pragma unroll
            for (int q = 0; q < KSPLIT; ++q)
                p += g_part[(size_t)q * (2 * Nn * Cc) + (size_t)m * Cc + k];
            sm.p3.pk[tid] = p;
        }
        __syncthreads();

        const float inv = (cnt > 0) ? 1.0f / (float)cnt : 0.0f;
        float sig = 0.f;
        for (int j = 0; j < cnt; ++j) {
            const int m = sm.p3.mlist[j];
            float p = 0.f;
#pragma unroll
            for (int q = 0; q < KSPLIT; ++q)
                p += g_part[(size_t)q * (2 * Nn * Cc) + (size_t)m * Cc + tid];
            const float d = p - sm.p3.pk[j];
            sig += d * d;
        }
        float y = bias[tid] + 0.25f * sig * inv;   // 0.5 * alpha
#pragma unroll
        for (int q = 0; q < KSPLIT; ++q)
            y += g_part[(size_t)q * (2 * Nn * Cc) + (size_t)(Nn + n) * Cc + tid];

        // block max
        float mmax = y;
#pragma unroll
        for (int o = 16; o; o >>= 1) mmax = fmaxf(mmax, __shfl_xor_sync(0xffffffffu, mmax, o));
        if (lane == 0) sm.p3.red[warp] = mmax;
        __syncthreads();
        mmax = sm.p3.red[0];
#pragma unroll
        for (int w = 1; w < 8; ++w) mmax = fmaxf(mmax, sm.p3.red[w]);
        __syncthreads();

        float e = expf(y - mmax);
#pragma unroll
        for (int o = 16; o; o >>= 1) e += __shfl_xor_sync(0xffffffffu, e, o);
        if (lane == 0) sm.p3.red[warp] = e;
        if (tid == k) sm.p3.yk = y;
        __syncthreads();
        if (tid == 0) {
            float tot = 0.f;
#pragma unroll
            for (int w = 0; w < 8; ++w) tot += sm.p3.red[w];
            const float loss_n = -(sm.p3.yk - mmax - logf(tot));
            atomicAdd(&g_lossSum, loss_n);
            __threadfence();
            const unsigned int prev = atomicAdd(&g_doneCnt, 1u);
            if (prev == NB - 1u) {
                const float tot2 = atomicAdd(&g_lossSum, 0.0f);  // ordered read
                out[0] = tot2 * (1.0f / (float)Nn);
            }
        }
    }
}

// ---------------------------------------------------------------------------
extern "C" void kernel_launch(void* const* d_in, const int* in_sizes, int n_in,
                              void* d_out, int out_size) {
    const float* fc_weight = (const float*)d_in[0];   // (2C, A)
    const float* fc_bias   = (const float*)d_in[1];   // (2C,)
    const float* s_feat    = (const float*)d_in[2];   // (N, A)
    const float* t_feat    = (const float*)d_in[3];   // (N, A)
    const int*   target_s  = (const int*)d_in[4];     // (N,)
    const int*   target_t  = (const int*)d_in[5];     // (N,)
    float* out = (float*)d_out;

    isda_fused_kernel<<<NB, NT>>>(fc_weight, fc_bias, s_feat, t_feat,
                                  target_s, target_t, out);
}

// round 6
// speedup vs baseline: 2.2355x; 1.0869x over previous
#include <cuda_runtime.h>
#include <math.h>

#define Nn 128
#define Cc 256
#define Aa 512
#define NB 128
#define NT 256
#define TS 66              // smem row stride (floats): even (8B-aligned rows)

// Scratch (device globals — no allocations allowed)
__device__ float g_X[2 * Nn * Aa];    // rows 0..127: U, 128..255: AUG
__device__ float g_PY[2 * Nn * Cc];   // accumulated: rows 0..127 P, 128..255 Y
__device__ float g_lossSum;
__device__ unsigned int g_doneCnt;
__device__ unsigned int g_barCount = 0;
__device__ unsigned int g_barGen = 0;

struct SmemP1 {
    int ts[Nn], tt[Nn];
    int listA[Nn], listT[Nn];
    int wA[4], wT[4];
};
struct SmemP2 { float Xs[64][TS]; };
struct SmemP3 {
    float pk[Nn];
    float red[8];
    float yk;
};
union __align__(16) SmemU { SmemP1 p1; SmemP2 p2; SmemP3 p3; };

// Grid-wide barrier: all NB blocks co-resident (single wave, NB <= #SMs).
__device__ __forceinline__ void grid_barrier() {
    __threadfence();
    __syncthreads();
    if (threadIdx.x == 0) {
        unsigned int gen = *(volatile unsigned int*)&g_barGen;
        unsigned int my = atomicAdd(&g_barCount, 1u);
        if (my == NB - 1u) {
            *(volatile unsigned int*)&g_barCount = 0u;
            __threadfence();
            atomicAdd(&g_barGen, 1u);
        } else {
            while (*(volatile unsigned int*)&g_barGen == gen) { }
        }
        __threadfence();
    }
    __syncthreads();
}

__global__ __launch_bounds__(NT, 1)
void isda_fused_kernel(const float* __restrict__ W,
                       const float* __restrict__ bias,
                       const float* __restrict__ s,
                       const float* __restrict__ t,
                       const int* __restrict__ ts,
                       const int* __restrict__ tt,
                       float* __restrict__ out)
{
    __shared__ SmemU sm;
    __shared__ float Wsm[64][TS];        // dedicated: prefetch overlaps phase 1
    __shared__ int   mlistP[Nn];         // persists P1 -> P3 (== listS)
    __shared__ int   wS[4];
    const int tid  = threadIdx.x;
    const int bid  = blockIdx.x;
    const int lane = tid & 31;
    const int warp = tid >> 5;

    // ---- First loads of the kernel: targets (tiny, needed by P1) ----
    int my_ts = 0, my_tt = 0;
    if (tid < Nn) { my_ts = ts[tid]; my_tt = tt[tid]; }

    // Phase-2 tile coordinates (known immediately)
    const int mt = bid & 3;
    const int ct = (bid >> 2) & 3;
    const int kt = bid >> 4;                 // 0..7
    const int m0 = mt * 64, c0 = ct * 64, kb = kt * 64;

    // ---- Prefetch W tile (independent of phase 1) ----
    float4 wr[4];
#pragma unroll
    for (int i = 0; i < 4; ++i) {
        const int idx = tid + i * 256;
        const int r = idx >> 4, kq = idx & 15;
        wr[i] = *(const float4*)&W[(size_t)(c0 + r) * Aa + kb + kq * 4];
    }

    // ---- Zero my slice of g_PY (128 float4 per block; threads 0-127) ----
    if (tid < 128)
        ((float4*)g_PY)[(size_t)bid * 128 + tid] = make_float4(0.f, 0.f, 0.f, 0.f);
    if (tid == 0 && bid == 0) { g_lossSum = 0.0f; g_doneCnt = 0u; }

    // ================= Phase 1: centering + augmented rows ==================
    int k2, nS;
    {
        const int n = bid;
        if (tid < Nn) { sm.p1.ts[tid] = my_ts; sm.p1.tt[tid] = my_tt; }
        __syncthreads();
        const int k1 = sm.p1.ts[n];
        k2 = sm.p1.tt[n];

        const bool valid = tid < Nn;
        const bool pA = valid && (my_ts == k1);
        const bool pS = valid && (my_ts == k2);
        const bool pT = valid && (my_tt == k2);
        const unsigned mA = __ballot_sync(0xffffffffu, pA);
        const unsigned mS = __ballot_sync(0xffffffffu, pS);
        const unsigned mT = __ballot_sync(0xffffffffu, pT);
        if (lane == 0 && warp < 4) {
            sm.p1.wA[warp] = __popc(mA);
            wS[warp]       = __popc(mS);
            sm.p1.wT[warp] = __popc(mT);
        }
        __syncthreads();
        const unsigned lt = (1u << lane) - 1u;
        if (warp < 4) {
            int bA = 0, bS = 0, bT = 0;
#pragma unroll
            for (int w = 0; w < 4; ++w)
                if (w < warp) { bA += sm.p1.wA[w]; bS += wS[w]; bT += sm.p1.wT[w]; }
            if (pA) sm.p1.listA[bA + __popc(mA & lt)] = tid;
            if (pS) mlistP[bS + __popc(mS & lt)] = tid;
            if (pT) sm.p1.listT[bT + __popc(mT & lt)] = tid;
        }
        const int nA = sm.p1.wA[0] + sm.p1.wA[1] + sm.p1.wA[2] + sm.p1.wA[3];
        nS = wS[0] + wS[1] + wS[2] + wS[3];
        const int nT = sm.p1.wT[0] + sm.p1.wT[1] + sm.p1.wT[2] + sm.p1.wT[3];
        __syncthreads();

        if (tid < 128) {
            // X[row n] = U[n] = s[n] - classmean_s(ts[n])
            const int a4 = tid;
            const float4 me = ((const float4*)(s + (size_t)n * Aa))[a4];
            float sx = 0.f, sy = 0.f, sz = 0.f, sw = 0.f;
#pragma unroll 4
            for (int j = 0; j < nA; ++j) {
                const float4 v = ((const float4*)(s + (size_t)sm.p1.listA[j] * Aa))[a4];
                sx += v.x; sy += v.y; sz += v.z; sw += v.w;
            }
            const float invA = 1.0f / (float)nA;   // nA >= 1 (n itself)
            float4 u;
            u.x = me.x - sx * invA; u.y = me.y - sy * invA;
            u.z = me.z - sz * invA; u.w = me.w - sw * invA;
            ((float4*)(g_X + (size_t)n * Aa))[a4] = u;
        } else {
            // X[row 128+n] = AUG[n] = 0.5*( meanS(tt[n]) [0 if empty] + meanT(tt[n]) )
            const int a4 = tid - 128;
            float ax = 0.f, ay = 0.f, az = 0.f, aw = 0.f;
#pragma unroll 4
            for (int j = 0; j < nS; ++j) {
                const float4 v = ((const float4*)(s + (size_t)mlistP[j] * Aa))[a4];
                ax += v.x; ay += v.y; az += v.z; aw += v.w;
            }
            float bx = 0.f, by = 0.f, bz = 0.f, bw = 0.f;
#pragma unroll 4
            for (int j = 0; j < nT; ++j) {
                const float4 v = ((const float4*)(t + (size_t)sm.p1.listT[j] * Aa))[a4];
                bx += v.x; by += v.y; bz += v.z; bw += v.w;
            }
            const float invS = (nS > 0) ? 1.0f / (float)nS : 0.0f;  // w_cv zeroing
            const float invT = 1.0f / (float)nT;                    // nT >= 1
            float4 g;
            g.x = 0.5f * (ax * invS + bx * invT);
            g.y = 0.5f * (ay * invS + by * invT);
            g.z = 0.5f * (az * invS + bz * invT);
            g.w = 0.5f * (aw * invS + bw * invT);
            ((float4*)(g_X + (size_t)(Nn + n) * Aa))[a4] = g;
        }
    }

    // Park prefetched W tile into smem (loads overlapped with all of P1)
#pragma unroll
    for (int i = 0; i < 4; ++i) {
        const int idx = tid + i * 256;
        const int r = idx >> 4, kq = idx & 15;
        *(float2*)&Wsm[r][kq * 4]     = make_float2(wr[i].x, wr[i].y);
        *(float2*)&Wsm[r][kq * 4 + 2] = make_float2(wr[i].z, wr[i].w);
    }
    grid_barrier();

    // ====== Phase 2: 256x256x512 GEMM, 64x64 tiles, 8-way K-split ==========
    {
        // Stage X tile
#pragma unroll
        for (int i = 0; i < 4; ++i) {
            const int idx = tid + i * 256;
            const int r = idx >> 4, kq = idx & 15;
            const float4 v = *(const float4*)&g_X[(size_t)(m0 + r) * Aa + kb + kq * 4];
            *(float2*)&sm.p2.Xs[r][kq * 4]     = make_float2(v.x, v.y);
            *(float2*)&sm.p2.Xs[r][kq * 4 + 2] = make_float2(v.z, v.w);
        }
        __syncthreads();

        const int tx = tid & 15;          // c sub-index
        const int ty = tid >> 4;          // m sub-index
        unsigned long long acc[16];
#pragma unroll
        for (int i = 0; i < 16; ++i) acc[i] = 0ull;

#pragma unroll 4
        for (int kk = 0; kk < 64; kk += 2) {
            unsigned long long xv[4], wv[4];
#pragma unroll
            for (int i = 0; i < 4; ++i)
                xv[i] = *(const unsigned long long*)&sm.p2.Xs[ty + 16 * i][kk];
#pragma unroll
            for (int u = 0; u < 4; ++u)
                wv[u] = *(const unsigned long long*)&Wsm[tx + 16 * u][kk];
#pragma unroll
            for (int i = 0; i < 4; ++i)
#pragma unroll
                for (int u = 0; u < 4; ++u)
                    asm("fma.rn.f32x2 %0, %1, %2, %0;"
                        : "+l"(acc[i * 4 + u]) : "l"(xv[i]), "l"(wv[u]));
        }

#pragma unroll
        for (int i = 0; i < 4; ++i)
#pragma unroll
            for (int u = 0; u < 4; ++u) {
                const unsigned long long a = acc[i * 4 + u];
                const float lo = __uint_as_float((unsigned int)(a & 0xffffffffull));
                const float hi = __uint_as_float((unsigned int)(a >> 32));
                atomicAdd(&g_PY[(size_t)(m0 + ty + 16 * i) * Cc + c0 + tx + 16 * u],
                          lo + hi);
            }
    }
    grid_barrier();

    // ========= Phase 3: sigma + log-softmax + NLL + last-block mean =========
    {
        const int n = bid;
        const int k = k2;                 // tt[n], persisted from P1
        const int cnt = nS;               // |{m : ts[m]==k}|, persisted
        if (tid < cnt) sm.p3.pk[tid] = g_PY[(size_t)mlistP[tid] * Cc + k];
        __syncthreads();

        const float inv = (cnt > 0) ? 1.0f / (float)cnt : 0.0f;
        float sig = 0.f;
        for (int j = 0; j < cnt; ++j) {
            const float d = g_PY[(size_t)mlistP[j] * Cc + tid] - sm.p3.pk[j];
            sig += d * d;
        }
        float y = g_PY[(size_t)(Nn + n) * Cc + tid] + bias[tid] + 0.25f * sig * inv;

        // block max
        float mmax = y;
#pragma unroll
        for (int o = 16; o; o >>= 1) mmax = fmaxf(mmax, __shfl_xor_sync(0xffffffffu, mmax, o));
        if (lane == 0) sm.p3.red[warp] = mmax;
        __syncthreads();
        mmax = sm.p3.red[0];
#pragma unroll
        for (int w = 1; w < 8; ++w) mmax = fmaxf(mmax, sm.p3.red[w]);
        __syncthreads();

        float e = expf(y - mmax);
#pragma unroll
        for (int o = 16; o; o >>= 1) e += __shfl_xor_sync(0xffffffffu, e, o);
        if (lane == 0) sm.p3.red[warp] = e;
        if (tid == k) sm.p3.yk = y;
        __syncthreads();
        if (tid == 0) {
            float tot = 0.f;
#pragma unroll
            for (int w = 0; w < 8; ++w) tot += sm.p3.red[w];
            const float loss_n = -(sm.p3.yk - mmax - logf(tot));
            atomicAdd(&g_lossSum, loss_n);
            __threadfence();
            const unsigned int prev = atomicAdd(&g_doneCnt, 1u);
            if (prev == NB - 1u) {
                const float tot2 = atomicAdd(&g_lossSum, 0.0f);  // ordered read
                out[0] = tot2 * (1.0f / (float)Nn);
            }
        }
    }
}

// ---------------------------------------------------------------------------
extern "C" void kernel_launch(void* const* d_in, const int* in_sizes, int n_in,
                              void* d_out, int out_size) {
    const float* fc_weight = (const float*)d_in[0];   // (2C, A)
    const float* fc_bias   = (const float*)d_in[1];   // (2C,)
    const float* s_feat    = (const float*)d_in[2];   // (N, A)
    const float* t_feat    = (const float*)d_in[3];   // (N, A)
    const int*   target_s  = (const int*)d_in[4];     // (N,)
    const int*   target_t  = (const int*)d_in[5];     // (N,)
    float* out = (float*)d_out;

    isda_fused_kernel<<<NB, NT>>>(fc_weight, fc_bias, s_feat, t_feat,
                                  target_s, target_t, out);
}

// round 7
// speedup vs baseline: 2.2442x; 1.0039x over previous
#include <cuda_runtime.h>
#include <math.h>

#define Nn 128
#define Cc 256
#define Aa 512
#define NB 128
#define NT 256
#define TS 66              // smem row stride (floats): even (8B-aligned rows)

// Scratch (device globals — no allocations allowed). All sync state is
// self-cleaning (reset by the last-done block) so graph replays are identical.
__device__ float g_GH[2 * Nn * Cc];     // rows 0..127: G = s@W^T, 128..255: H = t@W^T
__device__ float g_lossSum;             // zero-init; reset each run by last block
__device__ unsigned int g_doneCnt;      // idem
__device__ unsigned int g_tileFlag[16]; // per output tile: kt==0 partial stored
__device__ unsigned int g_barCount[32]; // [0] used; padded to own L2 line
__device__ unsigned int g_barGen[32];   // [0] used; padded to own L2 line

struct SmemG { float Xs[64][TS]; float Ws[64][TS]; };
struct SmemB {
    int ts[Nn], tt[Nn];
    int mlist[Nn], tlist[Nn];
    float pk[Nn];
    float red[8];
    float yk;
    int wM[4], wT[4];
};
union __align__(16) SmemU { SmemG g; SmemB b; };

// Grid-wide barrier: all NB blocks co-resident (single wave, NB <= #SMs).
__device__ __forceinline__ void grid_barrier() {
    __threadfence();
    __syncthreads();
    if (threadIdx.x == 0) {
        unsigned int gen = *(volatile unsigned int*)&g_barGen[0];
        unsigned int my = atomicAdd(&g_barCount[0], 1u);
        if (my == NB - 1u) {
            *(volatile unsigned int*)&g_barCount[0] = 0u;
            __threadfence();
            atomicAdd(&g_barGen[0], 1u);
        } else {
            while (*(volatile unsigned int*)&g_barGen[0] == gen) { }
        }
        __threadfence();
    }
    __syncthreads();
}

__global__ __launch_bounds__(NT, 1)
void isda_fused_kernel(const float* __restrict__ W,
                       const float* __restrict__ bias,
                       const float* __restrict__ s,
                       const float* __restrict__ t,
                       const int* __restrict__ ts,
                       const int* __restrict__ tt,
                       float* __restrict__ out)
{
    __shared__ SmemU sm;
    const int tid  = threadIdx.x;
    const int bid  = blockIdx.x;
    const int lane = tid & 31;
    const int warp = tid >> 5;

    // GEMM tile coordinates: 16 output tiles (64x64) x 8-way K-split
    const int mt = bid & 3;                  // row tile of [s;t] (256 rows)
    const int ct = (bid >> 2) & 3;
    const int kt = bid >> 4;                 // 0..7
    const int m0 = mt * 64, c0 = ct * 64, kb = kt * 64;
    const int tileId = bid & 15;

    // ---- Cycle-0 prefetch: GEMM operands are RAW INPUTS (no dependencies) ----
    const float* xbase = (mt < 2) ? (s + (size_t)m0 * Aa)
                                  : (t + (size_t)(m0 - 128) * Aa);
    int my_ts = 0, my_tt = 0;
    if (tid < Nn) { my_ts = ts[tid]; my_tt = tt[tid]; }
    float4 xr[4], wr[4];
#pragma unroll
    for (int i = 0; i < 4; ++i) {
        const int idx = tid + i * 256;
        const int r = idx >> 4, kq = idx & 15;
        xr[i] = *(const float4*)&xbase[(size_t)r * Aa + kb + kq * 4];
        wr[i] = *(const float4*)&W[(size_t)(c0 + r) * Aa + kb + kq * 4];
    }
#pragma unroll
    for (int i = 0; i < 4; ++i) {
        const int idx = tid + i * 256;
        const int r = idx >> 4, kq = idx & 15;
        *(float2*)&sm.g.Xs[r][kq * 4]     = make_float2(xr[i].x, xr[i].y);
        *(float2*)&sm.g.Xs[r][kq * 4 + 2] = make_float2(xr[i].z, xr[i].w);
        *(float2*)&sm.g.Ws[r][kq * 4]     = make_float2(wr[i].x, wr[i].y);
        *(float2*)&sm.g.Ws[r][kq * 4 + 2] = make_float2(wr[i].z, wr[i].w);
    }
    __syncthreads();

    // ================= Phase 1: [G;H] = [s;t] @ W[:C]^T =====================
    {
        const int tx = tid & 15;          // c sub-index
        const int ty = tid >> 4;          // m sub-index
        unsigned long long acc[16];
#pragma unroll
        for (int i = 0; i < 16; ++i) acc[i] = 0ull;

#pragma unroll 4
        for (int kk = 0; kk < 64; kk += 2) {
            unsigned long long xv[4], wv[4];
#pragma unroll
            for (int i = 0; i < 4; ++i)
                xv[i] = *(const unsigned long long*)&sm.g.Xs[ty + 16 * i][kk];
#pragma unroll
            for (int u = 0; u < 4; ++u)
                wv[u] = *(const unsigned long long*)&sm.g.Ws[tx + 16 * u][kk];
#pragma unroll
            for (int i = 0; i < 4; ++i)
#pragma unroll
                for (int u = 0; u < 4; ++u)
                    asm("fma.rn.f32x2 %0, %1, %2, %0;"
                        : "+l"(acc[i * 4 + u]) : "l"(xv[i]), "l"(wv[u]));
        }

        float r2[16];
#pragma unroll
        for (int i = 0; i < 16; ++i) {
            const unsigned long long a = acc[i];
            r2[i] = __uint_as_float((unsigned int)(a & 0xffffffffull)) +
                    __uint_as_float((unsigned int)(a >> 32));
        }

        if (kt == 0) {
            // First K-split block: plain store (no pre-zeroing needed)
#pragma unroll
            for (int i = 0; i < 4; ++i)
#pragma unroll
                for (int u = 0; u < 4; ++u)
                    g_GH[(size_t)(m0 + ty + 16 * i) * Cc + c0 + tx + 16 * u] = r2[i * 4 + u];
            __threadfence();
            __syncthreads();
            if (tid == 0) atomicExch(&g_tileFlag[tileId], 1u);
        } else {
            // Wait for base store of this tile, then accumulate
            if (tid == 0) {
                while (*(volatile unsigned int*)&g_tileFlag[tileId] == 0u) { }
            }
            __syncthreads();
            __threadfence();
#pragma unroll
            for (int i = 0; i < 4; ++i)
#pragma unroll
                for (int u = 0; u < 4; ++u)
                    atomicAdd(&g_GH[(size_t)(m0 + ty + 16 * i) * Cc + c0 + tx + 16 * u],
                              r2[i * 4 + u]);
        }
    }
    grid_barrier();

    // ===== Phase 2: class means in projection space + sigma + softmax =======
    {
        const int n = bid;
        if (tid < Nn) { sm.b.ts[tid] = my_ts; sm.b.tt[tid] = my_tt; }
        __syncthreads();
        const int k = sm.b.tt[n];

        const bool valid = tid < Nn;
        const bool pM = valid && (my_ts == k);   // s-samples in class k
        const bool pT = valid && (my_tt == k);   // t-samples in class k
        const unsigned mM = __ballot_sync(0xffffffffu, pM);
        const unsigned mT = __ballot_sync(0xffffffffu, pT);
        if (lane == 0 && warp < 4) { sm.b.wM[warp] = __popc(mM); sm.b.wT[warp] = __popc(mT); }
        __syncthreads();
        const unsigned lt = (1u << lane) - 1u;
        if (warp < 4) {
            int bM = 0, bT = 0;
#pragma unroll
            for (int w = 0; w < 4; ++w)
                if (w < warp) { bM += sm.b.wM[w]; bT += sm.b.wT[w]; }
            if (pM) sm.b.mlist[bM + __popc(mM & lt)] = tid;
            if (pT) sm.b.tlist[bT + __popc(mT & lt)] = tid;
        }
        const int cnt = sm.b.wM[0] + sm.b.wM[1] + sm.b.wM[2] + sm.b.wM[3];
        const int tnt = sm.b.wT[0] + sm.b.wT[1] + sm.b.wT[2] + sm.b.wT[3];
        __syncthreads();
        if (tid < cnt) sm.b.pk[tid] = g_GH[(size_t)sm.b.mlist[tid] * Cc + k];
        __syncthreads();

        const float invS = (cnt > 0) ? 1.0f / (float)cnt : 0.0f;  // w_cv zeroing
        const float invT = 1.0f / (float)tnt;                     // tnt >= 1 (n itself)
        const int c = tid;

        // Single pass: sums for mean + expanded-square sigma moments
        float sumpk = 0.f;
        for (int j = 0; j < cnt; ++j) sumpk += sm.b.pk[j];
        float sumG = 0.f, s1 = 0.f, s2 = 0.f;
        for (int j = 0; j < cnt; ++j) {
            const float gv = g_GH[(size_t)sm.b.mlist[j] * Cc + c];
            const float a = gv - sm.b.pk[j];
            sumG += gv; s1 += a; s2 += a * a;
        }
        float sumH = 0.f;
        for (int j = 0; j < tnt; ++j)
            sumH += g_GH[(size_t)(Nn + sm.b.tlist[j]) * Cc + c];

        const float dbar  = invS * (sumG - sumpk);   // Gbar[c] - Gbar[k]
        const float sigma = invS * (s2 - 2.0f * dbar * s1 + (float)cnt * dbar * dbar);
        float y = 0.5f * (sumG * invS + sumH * invT) + bias[c] + 0.25f * sigma;

        // block max
        float mmax = y;
#pragma unroll
        for (int o = 16; o; o >>= 1) mmax = fmaxf(mmax, __shfl_xor_sync(0xffffffffu, mmax, o));
        if (lane == 0) sm.b.red[warp] = mmax;
        __syncthreads();
        mmax = sm.b.red[0];
#pragma unroll
        for (int w = 1; w < 8; ++w) mmax = fmaxf(mmax, sm.b.red[w]);
        __syncthreads();

        float e = expf(y - mmax);
#pragma unroll
        for (int o = 16; o; o >>= 1) e += __shfl_xor_sync(0xffffffffu, e, o);
        if (lane == 0) sm.b.red[warp] = e;
        if (tid == k) sm.b.yk = y;
        __syncthreads();
        if (tid == 0) {
            float tot = 0.f;
#pragma unroll
            for (int w = 0; w < 8; ++w) tot += sm.b.red[w];
            const float loss_n = -(sm.b.yk - mmax - logf(tot));
            atomicAdd(&g_lossSum, loss_n);
            __threadfence();
            const unsigned int prev = atomicAdd(&g_doneCnt, 1u);
            if (prev == NB - 1u) {
                const float tot2 = atomicAdd(&g_lossSum, 0.0f);  // ordered read
                out[0] = tot2 * (1.0f / (float)Nn);
                // Self-clean state for the next (graph-replayed) run
                g_lossSum = 0.0f;
                *(volatile unsigned int*)&g_doneCnt = 0u;
#pragma unroll
                for (int i = 0; i < 16; ++i)
                    *(volatile unsigned int*)&g_tileFlag[i] = 0u;
            }
        }
    }
}

// ---------------------------------------------------------------------------
extern "C" void kernel_launch(void* const* d_in, const int* in_sizes, int n_in,
                              void* d_out, int out_size) {
    const float* fc_weight = (const float*)d_in[0];   // (2C, A)
    const float* fc_bias   = (const float*)d_in[1];   // (2C,)
    const float* s_feat    = (const float*)d_in[2];   // (N, A)
    const float* t_feat    = (const float*)d_in[3];   // (N, A)
    const int*   target_s  = (const int*)d_in[4];     // (N,)
    const int*   target_t  = (const int*)d_in[5];     // (N,)
    float* out = (float*)d_out;

    isda_fused_kernel<<<NB, NT>>>(fc_weight, fc_bias, s_feat, t_feat,
                                  target_s, target_t, out);
}

// round 8
// speedup vs baseline: 2.4328x; 1.0840x over previous
#include <cuda_runtime.h>
#include <math.h>

#define Nn 128
#define Cc 256
#define Aa 512
#define NB 128
#define NT 256
#define KSPLIT 8
#define TS 66              // smem row stride (floats): even (8B-aligned rows)

// Scratch (device globals — no allocations allowed). Sync state is
// self-cleaning (reset by last arriver) so graph replays are identical;
// generation counter is monotonic (never reset, only compared).
__device__ float g_part[KSPLIT * 2 * Nn * Cc]; // K-split partials of [G;H]
__device__ float g_loss[Nn];
// Tree A: mid barrier. Level-1: 16 counters on separate 128B lines.
__device__ unsigned int g_l1A[16 * 32];
__device__ unsigned int g_l2A;
__device__ unsigned int g_genA;                // monotonic across replays
// Tree B: completion detection for final reduction.
__device__ unsigned int g_l1B[16 * 32];
__device__ unsigned int g_l2B;

struct SmemG { float Xs[64][TS]; float Ws[64][TS]; };
struct SmemB {
    int ts[Nn], tt[Nn];
    int mlist[Nn], tlist[Nn];
    float pk[Nn];
    float red[8];
    float yk;
    int wM[4], wT[4];
};
union __align__(16) SmemU { SmemG g; SmemB b; };

// Tree grid barrier: all NB blocks co-resident (single wave, NB <= #SMs).
// Same-address atomic convoys are the enemy (27 cyc/op serialized): split
// arrivals 8-per-counter across 16 L2 lines, then 16 into one, then release.
__device__ __forceinline__ void grid_barrier_tree() {
    __threadfence();
    __syncthreads();
    if (threadIdx.x == 0) {
        const int grp = blockIdx.x >> 3;
        const unsigned int gen = *(volatile unsigned int*)&g_genA;
        const unsigned int p = atomicAdd(&g_l1A[grp * 32], 1u);
        if (p == 7u) {
            g_l1A[grp * 32] = 0u;             // last of group this run
            const unsigned int p2 = atomicAdd(&g_l2A, 1u);
            if (p2 == 15u) {
                g_l2A = 0u;
                __threadfence();
                atomicAdd(&g_genA, 1u);       // release
            } else {
                while (*(volatile unsigned int*)&g_genA == gen) { }
            }
        } else {
            while (*(volatile unsigned int*)&g_genA == gen) { }
        }
        __threadfence();
    }
    __syncthreads();
}

// Sum the 8 K-split partials for element [row, col] of [G;H].
__device__ __forceinline__ float sum8(int row, int col) {
    float v = 0.f;
#pragma unroll
    for (int q = 0; q < KSPLIT; ++q)
        v += g_part[q * (2 * Nn * Cc) + row * Cc + col];
    return v;
}

__global__ __launch_bounds__(NT, 1)
void isda_fused_kernel(const float* __restrict__ W,
                       const float* __restrict__ bias,
                       const float* __restrict__ s,
                       const float* __restrict__ t,
                       const int* __restrict__ ts,
                       const int* __restrict__ tt,
                       float* __restrict__ out)
{
    __shared__ SmemU sm;
    __shared__ int sh_last;
    const int tid  = threadIdx.x;
    const int bid  = blockIdx.x;
    const int lane = tid & 31;
    const int warp = tid >> 5;

    // GEMM tile coordinates: 16 output tiles (64x64) x 8-way K-split
    const int mt = bid & 3;                  // row tile of [s;t] (256 rows)
    const int ct = (bid >> 2) & 3;
    const int kt = bid >> 4;                 // 0..7
    const int m0 = mt * 64, c0 = ct * 64, kb = kt * 64;

    // ---- Cycle-0 prefetch: GEMM operands are RAW INPUTS (no dependencies) ----
    const float* xbase = (mt < 2) ? (s + (size_t)m0 * Aa)
                                  : (t + (size_t)(m0 - 128) * Aa);
    int my_ts = 0, my_tt = 0;
    if (tid < Nn) { my_ts = ts[tid]; my_tt = tt[tid]; }
    float4 xr[4], wr[4];
#pragma unroll
    for (int i = 0; i < 4; ++i) {
        const int idx = tid + i * 256;
        const int r = idx >> 4, kq = idx & 15;
        xr[i] = *(const float4*)&xbase[(size_t)r * Aa + kb + kq * 4];
        wr[i] = *(const float4*)&W[(size_t)(c0 + r) * Aa + kb + kq * 4];
    }
#pragma unroll
    for (int i = 0; i < 4; ++i) {
        const int idx = tid + i * 256;
        const int r = idx >> 4, kq = idx & 15;
        *(float2*)&sm.g.Xs[r][kq * 4]     = make_float2(xr[i].x, xr[i].y);
        *(float2*)&sm.g.Xs[r][kq * 4 + 2] = make_float2(xr[i].z, xr[i].w);
        *(float2*)&sm.g.Ws[r][kq * 4]     = make_float2(wr[i].x, wr[i].y);
        *(float2*)&sm.g.Ws[r][kq * 4 + 2] = make_float2(wr[i].z, wr[i].w);
    }
    __syncthreads();

    // ================= Phase 1: [G;H] = [s;t] @ W[:C]^T =====================
    {
        const int tx = tid & 15;          // c sub-index
        const int ty = tid >> 4;          // m sub-index
        unsigned long long acc[16];
#pragma unroll
        for (int i = 0; i < 16; ++i) acc[i] = 0ull;

#pragma unroll 4
        for (int kk = 0; kk < 64; kk += 2) {
            unsigned long long xv[4], wv[4];
#pragma unroll
            for (int i = 0; i < 4; ++i)
                xv[i] = *(const unsigned long long*)&sm.g.Xs[ty + 16 * i][kk];
#pragma unroll
            for (int u = 0; u < 4; ++u)
                wv[u] = *(const unsigned long long*)&sm.g.Ws[tx + 16 * u][kk];
#pragma unroll
            for (int i = 0; i < 4; ++i)
#pragma unroll
                for (int u = 0; u < 4; ++u)
                    asm("fma.rn.f32x2 %0, %1, %2, %0;"
                        : "+l"(acc[i * 4 + u]) : "l"(xv[i]), "l"(wv[u]));
        }

        // Plain stores to this kt's private partial buffer (no atomics/flags)
        float* base = g_part + (size_t)kt * (2 * Nn * Cc);
#pragma unroll
        for (int i = 0; i < 4; ++i)
#pragma unroll
            for (int u = 0; u < 4; ++u) {
                const unsigned long long a = acc[i * 4 + u];
                const float lo = __uint_as_float((unsigned int)(a & 0xffffffffull));
                const float hi = __uint_as_float((unsigned int)(a >> 32));
                base[(size_t)(m0 + ty + 16 * i) * Cc + c0 + tx + 16 * u] = lo + hi;
            }
    }
    grid_barrier_tree();

    // ===== Phase 2: class means in projection space + sigma + softmax =======
    {
        const int n = bid;
        if (tid < Nn) { sm.b.ts[tid] = my_ts; sm.b.tt[tid] = my_tt; }
        __syncthreads();
        const int k = sm.b.tt[n];

        const bool valid = tid < Nn;
        const bool pM = valid && (my_ts == k);   // s-samples in class k
        const bool pT = valid && (my_tt == k);   // t-samples in class k
        const unsigned mM = __ballot_sync(0xffffffffu, pM);
        const unsigned mT = __ballot_sync(0xffffffffu, pT);
        if (lane == 0 && warp < 4) { sm.b.wM[warp] = __popc(mM); sm.b.wT[warp] = __popc(mT); }
        __syncthreads();
        const unsigned lt = (1u << lane) - 1u;
        if (warp < 4) {
            int bM = 0, bT = 0;
#pragma unroll
            for (int w = 0; w < 4; ++w)
                if (w < warp) { bM += sm.b.wM[w]; bT += sm.b.wT[w]; }
            if (pM) sm.b.mlist[bM + __popc(mM & lt)] = tid;
            if (pT) sm.b.tlist[bT + __popc(mT & lt)] = tid;
        }
        const int cnt = sm.b.wM[0] + sm.b.wM[1] + sm.b.wM[2] + sm.b.wM[3];
        const int tnt = sm.b.wT[0] + sm.b.wT[1] + sm.b.wT[2] + sm.b.wT[3];
        __syncthreads();
        if (tid < cnt) sm.b.pk[tid] = sum8(sm.b.mlist[tid], k);
        __syncthreads();

        const float invS = (cnt > 0) ? 1.0f / (float)cnt : 0.0f;  // w_cv zeroing
        const float invT = 1.0f / (float)tnt;                     // tnt >= 1 (n itself)
        const int c = tid;

        // Single pass: sums for mean + expanded-square sigma moments
        float sumpk = 0.f;
        for (int j = 0; j < cnt; ++j) sumpk += sm.b.pk[j];
        float sumG = 0.f, s1 = 0.f, s2 = 0.f;
#pragma unroll 2
        for (int j = 0; j < cnt; ++j) {
            const float gv = sum8(sm.b.mlist[j], c);
            const float a = gv - sm.b.pk[j];
            sumG += gv; s1 += a; s2 += a * a;
        }
        float sumH = 0.f;
#pragma unroll 2
        for (int j = 0; j < tnt; ++j)
            sumH += sum8(Nn + sm.b.tlist[j], c);

        const float dbar  = invS * (sumG - sumpk);   // Gbar[c] - Gbar[k]
        const float sigma = invS * (s2 - 2.0f * dbar * s1 + (float)cnt * dbar * dbar);
        float y = 0.5f * (sumG * invS + sumH * invT) + bias[c] + 0.25f * sigma;

        // block max
        float mmax = y;
#pragma unroll
        for (int o = 16; o; o >>= 1) mmax = fmaxf(mmax, __shfl_xor_sync(0xffffffffu, mmax, o));
        if (lane == 0) sm.b.red[warp] = mmax;
        __syncthreads();
        mmax = sm.b.red[0];
#pragma unroll
        for (int w = 1; w < 8; ++w) mmax = fmaxf(mmax, sm.b.red[w]);
        __syncthreads();

        float e = expf(y - mmax);
#pragma unroll
        for (int o = 16; o; o >>= 1) e += __shfl_xor_sync(0xffffffffu, e, o);
        if (lane == 0) sm.b.red[warp] = e;
        if (tid == k) sm.b.yk = y;
        __syncthreads();
        if (tid == 0) {
            float tot = 0.f;
#pragma unroll
            for (int w = 0; w < 8; ++w) tot += sm.b.red[w];
            g_loss[n] = -(sm.b.yk - mmax - logf(tot));   // plain store
        }
    }

    // ===== Completion tree: final-arriving block reduces the mean ===========
    if (tid == 0) {
        sh_last = 0;
        __threadfence();                     // publish g_loss[n]
        const int grp = bid >> 3;
        const unsigned int p = atomicAdd(&g_l1B[grp * 32], 1u);
        if (p == 7u) {
            g_l1B[grp * 32] = 0u;
            const unsigned int p2 = atomicAdd(&g_l2B, 1u);
            if (p2 == 15u) { g_l2B = 0u; sh_last = 1; }
        }
    }
    __syncthreads();
    if (sh_last) {
        __threadfence();                     // acquire all g_loss stores
        float v = (tid < Nn) ? g_loss[tid] : 0.0f;
#pragma unroll
        for (int o = 16; o; o >>= 1) v += __shfl_xor_sync(0xffffffffu, v, o);
        if (lane == 0) sm.b.red[warp] = v;
        __syncthreads();
        if (tid == 0) {
            float tot = 0.f;
#pragma unroll
            for (int w = 0; w < 8; ++w) tot += sm.b.red[w];
            out[0] = tot * (1.0f / (float)Nn);
        }
    }
}

// ---------------------------------------------------------------------------
extern "C" void kernel_launch(void* const* d_in, const int* in_sizes, int n_in,
                              void* d_out, int out_size) {
    const float* fc_weight = (const float*)d_in[0];   // (2C, A)
    const float* fc_bias   = (const float*)d_in[1];   // (2C,)
    const float* s_feat    = (const float*)d_in[2];   // (N, A)
    const float* t_feat    = (const float*)d_in[3];   // (N, A)
    const int*   target_s  = (const int*)d_in[4];     // (N,)
    const int*   target_t  = (const int*)d_in[5];     // (N,)
    float* out = (float*)d_out;

    isda_fused_kernel<<<NB, NT>>>(fc_weight, fc_bias, s_feat, t_feat,
                                  target_s, target_t, out);
}